// round 9
// baseline (speedup 1.0000x reference)
#include <cuda_runtime.h>
#include <cuda_fp16.h>

#define NMAX 50000
#define NG 512

// ---- scratch (static __device__: no allocation allowed) ----
__device__ __align__(16) __half g_xh[NMAX * 64];   // x in half
__device__ __align__(16) __half g_aggh[NMAX * 64]; // neighbor-sum accumulator (half)
__device__ float    g_h[NMAX * 64];       // hidden after Linear1
__device__ float    g_stats[128];         // [0:64) sum, [64:128) sumsq
__device__ float    g_add[NG * 64];       // segment sum pool
__device__ unsigned g_max[NG * 64];       // segment max pool (relu>=0 -> uint order ok)
__device__ int      g_isI32;              // 1 if indices are int32, 0 if int64

// ---- TF32 MMA helpers ----
__device__ __forceinline__ unsigned cvt_tf32(float f) {
    unsigned u;
    asm("cvt.rna.tf32.f32 %0, %1;" : "=r"(u) : "f"(f));
    return u;
}
__device__ __forceinline__ void mma_tf32(float& c0, float& c1, float& c2, float& c3,
                                         unsigned a0, unsigned a1, unsigned a2, unsigned a3,
                                         unsigned b0, unsigned b1) {
    asm("mma.sync.aligned.m16n8k8.row.col.f32.tf32.tf32.f32 "
        "{%0,%1,%2,%3}, {%4,%5,%6,%7}, {%8,%9}, {%0,%1,%2,%3};"
        : "+f"(c0), "+f"(c1), "+f"(c2), "+f"(c3)
        : "r"(a0), "r"(a1), "r"(a2), "r"(a3), "r"(b0), "r"(b1));
}
__device__ __forceinline__ int batch_of(const void* batch, int r, int isI32) {
    return isI32 ? ((const int*)batch)[r] : (int)((const long long*)batch)[r];
}

// ============================================================
// K0: pack x->half, zero accumulator/stats/pools, probe idx dtype
// ============================================================
__global__ void k_init(const float* __restrict__ x, const int* __restrict__ ei32, int n8) {
    int tid = blockIdx.x * blockDim.x + threadIdx.x;
    if (tid == 0) {
        int nz = 0;
        #pragma unroll 4
        for (int i = 0; i < 256; i++) nz |= ei32[2 * i + 1];
        g_isI32 = (nz != 0) ? 1 : 0;
    }
    if (tid < n8) {
        const float4* xp = (const float4*)(x + (size_t)tid * 8);
        float4 a = xp[0], b = xp[1];
        __half2 h0 = __float22half2_rn(make_float2(a.x, a.y));
        __half2 h1 = __float22half2_rn(make_float2(a.z, a.w));
        __half2 h2 = __float22half2_rn(make_float2(b.x, b.y));
        __half2 h3 = __float22half2_rn(make_float2(b.z, b.w));
        uint4 o;
        o.x = *(unsigned*)&h0; o.y = *(unsigned*)&h1;
        o.z = *(unsigned*)&h2; o.w = *(unsigned*)&h3;
        *(uint4*)(g_xh + (size_t)tid * 8) = o;
        *(uint4*)(g_aggh + (size_t)tid * 8) = make_uint4(0u, 0u, 0u, 0u);
    }
    if (tid < 128) g_stats[tid] = 0.0f;
    if (tid < NG * 64) { g_add[tid] = 0.0f; g_max[tid] = 0u; }
}

// ============================================================
// K1: edge scatter  aggh[dst] += xh[src]
// ============================================================
__global__ void k_edges(const void* __restrict__ ei, int n_edges) {
    int tid = blockIdx.x * blockDim.x + threadIdx.x;
    if (tid >= n_edges * 8) return;
    int e = tid >> 3;
    int c = tid & 7;
    int s, d;
    if (g_isI32) {
        const int* p = (const int*)ei;
        s = p[e]; d = p[n_edges + e];
    } else {
        const long long* p = (const long long*)ei;
        s = (int)p[e]; d = (int)p[n_edges + e];
    }
    uint4 v = *(const uint4*)(g_xh + ((size_t)s << 6) + (c << 3));
    __half* o = g_aggh + ((size_t)d << 6) + (c << 3);
    asm volatile("red.global.add.noftz.v4.f16x2 [%0], {%1, %2, %3, %4};"
                 :: "l"(o), "r"(v.x), "r"(v.y), "r"(v.z), "r"(v.w)
                 : "memory");
}

// ============================================================
// K2: h = (x + aggh) @ W1 + b1  via tf32 MMA; BN stats
// 256 thr = 8 warps; warp (mtile 0..3, ngrp 0..1); 64-row tile
// ============================================================
__global__ __launch_bounds__(256) void k_gemm1(const float* __restrict__ x,
                                               const float* __restrict__ W1,
                                               const float* __restrict__ b1, int n_nodes) {
    __shared__ unsigned sA[64 * 68];   // tf32, [row][k] pitch 68
    __shared__ unsigned sW[64 * 68];   // tf32, TRANSPOSED [n][k] pitch 68
    __shared__ float sSum[64], sSq[64];
    int tid = threadIdx.x;
    int row0 = blockIdx.x * 64;

    // W1 is [k=64][n=64] row-major; store transposed+converted
    for (int i = tid; i < 4096; i += 256) {
        int k = i >> 6, n = i & 63;
        sW[n * 68 + k] = cvt_tf32(W1[i]);
    }
    if (tid < 64) { sSum[tid] = 0.0f; sSq[tid] = 0.0f; }
    for (int i = tid; i < 1024; i += 256) {
        int r = i >> 4, c4 = i & 15, gr = row0 + r;
        float4 v = make_float4(0.f, 0.f, 0.f, 0.f);
        if (gr < n_nodes) {
            v = *(const float4*)(x + (size_t)gr * 64 + c4 * 4);
            uint2 hh = *(const uint2*)(g_aggh + (size_t)gr * 64 + c4 * 4);
            float2 f0 = __half22float2(*(__half2*)&hh.x);
            float2 f1 = __half22float2(*(__half2*)&hh.y);
            v.x += f0.x; v.y += f0.y; v.z += f1.x; v.w += f1.y;
        }
        unsigned* p = &sA[r * 68 + c4 * 4];
        p[0] = cvt_tf32(v.x); p[1] = cvt_tf32(v.y);
        p[2] = cvt_tf32(v.z); p[3] = cvt_tf32(v.w);
    }
    __syncthreads();

    int warp = tid >> 5, lane = tid & 31;
    int mtile = warp & 3, ngrp = warp >> 2;
    int gid = lane >> 2, tig = lane & 3;
    int arow = mtile * 16 + gid;

    float acc[4][4];
    #pragma unroll
    for (int j = 0; j < 4; j++) {
        int col0 = (ngrp * 4 + j) * 8 + tig * 2;
        float bb0 = b1[col0], bb1 = b1[col0 + 1];
        acc[j][0] = bb0; acc[j][1] = bb1; acc[j][2] = bb0; acc[j][3] = bb1;
    }

    #pragma unroll
    for (int kk = 0; kk < 8; kk++) {
        int k0 = kk * 8;
        unsigned a0 = sA[arow * 68 + k0 + tig];
        unsigned a1 = sA[(arow + 8) * 68 + k0 + tig];
        unsigned a2 = sA[arow * 68 + k0 + tig + 4];
        unsigned a3 = sA[(arow + 8) * 68 + k0 + tig + 4];
        #pragma unroll
        for (int j = 0; j < 4; j++) {
            int bcol = (ngrp * 4 + j) * 8 + gid;
            unsigned b0 = sW[bcol * 68 + k0 + tig];
            unsigned b1r = sW[bcol * 68 + k0 + tig + 4];
            mma_tf32(acc[j][0], acc[j][1], acc[j][2], acc[j][3], a0, a1, a2, a3, b0, b1r);
        }
    }

    int r0 = row0 + mtile * 16 + gid;
    int r1 = r0 + 8;
    bool v0 = (r0 < n_nodes), v1 = (r1 < n_nodes);
    #pragma unroll
    for (int j = 0; j < 4; j++) {
        int col0 = (ngrp * 4 + j) * 8 + tig * 2;
        float s0 = 0.f, s1 = 0.f, q0 = 0.f, q1 = 0.f;
        if (v0) {
            *(float2*)(g_h + (size_t)r0 * 64 + col0) = make_float2(acc[j][0], acc[j][1]);
            s0 += acc[j][0]; s1 += acc[j][1];
            q0 += acc[j][0] * acc[j][0]; q1 += acc[j][1] * acc[j][1];
        }
        if (v1) {
            *(float2*)(g_h + (size_t)r1 * 64 + col0) = make_float2(acc[j][2], acc[j][3]);
            s0 += acc[j][2]; s1 += acc[j][3];
            q0 += acc[j][2] * acc[j][2]; q1 += acc[j][3] * acc[j][3];
        }
        atomicAdd(&sSum[col0], s0);   atomicAdd(&sSum[col0 + 1], s1);
        atomicAdd(&sSq[col0], q0);    atomicAdd(&sSq[col0 + 1], q1);
    }
    __syncthreads();
    if (tid < 64) {
        atomicAdd(&g_stats[tid], sSum[tid]);
        atomicAdd(&g_stats[64 + tid], sSq[tid]);
    }
}

// ============================================================
// K4: h2 = relu(relu(bn(h)) @ W2 + b2) via tf32 MMA; pooled
// ============================================================
__global__ __launch_bounds__(256) void k_gemm2(const float* __restrict__ W2,
                                               const float* __restrict__ b2,
                                               const float* __restrict__ gamma,
                                               const float* __restrict__ beta,
                                               const void* __restrict__ batch,
                                               int n_nodes, float inv_n) {
    __shared__ unsigned sA[64 * 68];
    __shared__ unsigned sW[64 * 68];
    __shared__ float sScale[64], sShift[64];
    int tid = threadIdx.x;
    int row0 = blockIdx.x * 64;

    for (int i = tid; i < 4096; i += 256) {
        int k = i >> 6, n = i & 63;
        sW[n * 68 + k] = cvt_tf32(W2[i]);
    }
    if (tid < 64) {
        float mean = g_stats[tid] * inv_n;
        float var  = g_stats[64 + tid] * inv_n - mean * mean;
        float a = gamma[tid] * rsqrtf(var + 1e-5f);
        sScale[tid] = a;
        sShift[tid] = beta[tid] - mean * a;
    }
    __syncthreads();
    for (int i = tid; i < 1024; i += 256) {
        int r = i >> 4, c4 = i & 15, gr = row0 + r, k0 = c4 * 4;
        float4 v = make_float4(0.f, 0.f, 0.f, 0.f);
        if (gr < n_nodes) {
            v = *(const float4*)(g_h + (size_t)gr * 64 + k0);
            v.x = fmaxf(v.x * sScale[k0 + 0] + sShift[k0 + 0], 0.f);
            v.y = fmaxf(v.y * sScale[k0 + 1] + sShift[k0 + 1], 0.f);
            v.z = fmaxf(v.z * sScale[k0 + 2] + sShift[k0 + 2], 0.f);
            v.w = fmaxf(v.w * sScale[k0 + 3] + sShift[k0 + 3], 0.f);
        }
        unsigned* p = &sA[r * 68 + k0];
        p[0] = cvt_tf32(v.x); p[1] = cvt_tf32(v.y);
        p[2] = cvt_tf32(v.z); p[3] = cvt_tf32(v.w);
    }
    __syncthreads();

    int warp = tid >> 5, lane = tid & 31;
    int mtile = warp & 3, ngrp = warp >> 2;
    int gid = lane >> 2, tig = lane & 3;
    int arow = mtile * 16 + gid;

    float acc[4][4];
    #pragma unroll
    for (int j = 0; j < 4; j++) {
        int col0 = (ngrp * 4 + j) * 8 + tig * 2;
        float bb0 = b2[col0], bb1 = b2[col0 + 1];
        acc[j][0] = bb0; acc[j][1] = bb1; acc[j][2] = bb0; acc[j][3] = bb1;
    }

    #pragma unroll
    for (int kk = 0; kk < 8; kk++) {
        int k0 = kk * 8;
        unsigned a0 = sA[arow * 68 + k0 + tig];
        unsigned a1 = sA[(arow + 8) * 68 + k0 + tig];
        unsigned a2 = sA[arow * 68 + k0 + tig + 4];
        unsigned a3 = sA[(arow + 8) * 68 + k0 + tig + 4];
        #pragma unroll
        for (int j = 0; j < 4; j++) {
            int bcol = (ngrp * 4 + j) * 8 + gid;
            unsigned b0 = sW[bcol * 68 + k0 + tig];
            unsigned b1r = sW[bcol * 68 + k0 + tig + 4];
            mma_tf32(acc[j][0], acc[j][1], acc[j][2], acc[j][3], a0, a1, a2, a3, b0, b1r);
        }
    }

    // pooling epilogue: rows r0, r1 = r0+8; merge when same graph
    int r0 = row0 + mtile * 16 + gid;
    int r1 = r0 + 8;
    int isI32 = g_isI32;
    int bi0 = (r0 < n_nodes) ? batch_of(batch, r0, isI32) : -1;
    int bi1 = (r1 < n_nodes) ? batch_of(batch, r1, isI32) : -1;
    #pragma unroll
    for (int j = 0; j < 4; j++) {
        int col0 = (ngrp * 4 + j) * 8 + tig * 2;
        float v00 = fmaxf(acc[j][0], 0.f), v01 = fmaxf(acc[j][1], 0.f);
        float v10 = fmaxf(acc[j][2], 0.f), v11 = fmaxf(acc[j][3], 0.f);
        if (bi0 >= 0 && bi0 == bi1) {
            float* pa = g_add + (size_t)bi0 * 64 + col0;
            asm volatile("red.global.add.v2.f32 [%0], {%1, %2};"
                         :: "l"(pa), "f"(v00 + v10), "f"(v01 + v11) : "memory");
            unsigned* pm = g_max + (size_t)bi0 * 64 + col0;
            atomicMax(pm,     __float_as_uint(fmaxf(v00, v10)));
            atomicMax(pm + 1, __float_as_uint(fmaxf(v01, v11)));
        } else {
            if (bi0 >= 0) {
                float* pa = g_add + (size_t)bi0 * 64 + col0;
                asm volatile("red.global.add.v2.f32 [%0], {%1, %2};"
                             :: "l"(pa), "f"(v00), "f"(v01) : "memory");
                unsigned* pm = g_max + (size_t)bi0 * 64 + col0;
                atomicMax(pm, __float_as_uint(v00));
                atomicMax(pm + 1, __float_as_uint(v01));
            }
            if (bi1 >= 0) {
                float* pa = g_add + (size_t)bi1 * 64 + col0;
                asm volatile("red.global.add.v2.f32 [%0], {%1, %2};"
                             :: "l"(pa), "f"(v10), "f"(v11) : "memory");
                unsigned* pm = g_max + (size_t)bi1 * 64 + col0;
                atomicMax(pm, __float_as_uint(v10));
                atomicMax(pm + 1, __float_as_uint(v11));
            }
        }
    }
}

// ============================================================
// K5: head MLP, 4 graphs per block
// ============================================================
__global__ __launch_bounds__(128) void k_final(const float* __restrict__ Wl1,
                                               const float* __restrict__ bl1,
                                               const float* __restrict__ Wl2,
                                               const float* __restrict__ bl2,
                                               float* __restrict__ out, int out_size) {
    int g0 = blockIdx.x * 4;
    int j = threadIdx.x;
    __shared__ float sg[4][128];
    __shared__ float red[4][128];
    #pragma unroll
    for (int q = 0; q < 4; q++) {
        int g = g0 + q;
        sg[q][j] = (j < 64) ? g_add[g * 64 + j]
                            : __uint_as_float(g_max[g * 64 + (j - 64)]);
    }
    __syncthreads();
    float bj = bl1[j];
    float t[4] = {bj, bj, bj, bj};
    #pragma unroll 4
    for (int k = 0; k < 128; k++) {
        float w = Wl1[k * 128 + j];
        #pragma unroll
        for (int q = 0; q < 4; q++) t[q] += sg[q][k] * w;
    }
    float w2 = Wl2[j];
    #pragma unroll
    for (int q = 0; q < 4; q++) red[q][j] = fmaxf(t[q], 0.f) * w2;
    __syncthreads();
    for (int sft = 64; sft > 0; sft >>= 1) {
        if (j < sft) {
            #pragma unroll
            for (int q = 0; q < 4; q++) red[q][j] += red[q][j + sft];
        }
        __syncthreads();
    }
    if (j < 4) {
        float logit = red[j][0] + bl2[0];
        int g = g0 + j;
        out[g] = 1.0f / (1.0f + expf(-logit));
        if (out_size >= 2 * NG) out[NG + g] = logit;
    }
}

// ============================================================
extern "C" void kernel_launch(void* const* d_in, const int* in_sizes, int n_in,
                              void* d_out, int out_size) {
    const float* x     = (const float*)d_in[0];
    const void*  ei    = d_in[1];
    const void*  batch = d_in[2];
    const float* W1    = (const float*)d_in[3];
    const float* b1    = (const float*)d_in[4];
    const float* gamma = (const float*)d_in[5];
    const float* beta  = (const float*)d_in[6];
    const float* W2    = (const float*)d_in[7];
    const float* b2    = (const float*)d_in[8];
    const float* Wl1   = (const float*)d_in[9];
    const float* bl1   = (const float*)d_in[10];
    const float* Wl2   = (const float*)d_in[11];
    const float* bl2   = (const float*)d_in[12];
    float* out = (float*)d_out;

    int n_nodes = in_sizes[0] / 64;
    if (n_nodes > NMAX) n_nodes = NMAX;
    int n_edges = in_sizes[1] / 2;

    int n8 = n_nodes * 8;
    int initN = (n8 > NG * 64) ? n8 : NG * 64;
    k_init<<<(initN + 255) / 256, 256>>>(x, (const int*)ei, n8);

    long long etot = (long long)n_edges * 8;
    k_edges<<<(int)((etot + 255) / 256), 256>>>(ei, n_edges);

    int nb = (n_nodes + 63) / 64;
    k_gemm1<<<nb, 256>>>(x, W1, b1, n_nodes);
    k_gemm2<<<nb, 256>>>(W2, b2, gamma, beta, batch, n_nodes, 1.0f / (float)n_nodes);
    k_final<<<NG / 4, 128>>>(Wl1, bl1, Wl2, bl2, out, out_size);
}

// round 10
// speedup vs baseline: 1.0267x; 1.0267x over previous
#include <cuda_runtime.h>
#include <cuda_fp16.h>

#define NMAX 50000
#define NG 512

// ---- scratch (static __device__: no allocation allowed) ----
__device__ __align__(16) __half g_xh[NMAX * 64];   // x in half
__device__ __align__(16) __half g_aggh[NMAX * 64]; // neighbor-sum accumulator (half)
__device__ float    g_h[NMAX * 64];       // hidden after Linear1
__device__ float    g_stats[128];         // [0:64) sum, [64:128) sumsq
__device__ float    g_add[NG * 64];       // segment sum pool
__device__ unsigned g_max[NG * 64];       // segment max pool
__device__ int      g_isI32;
__device__ __align__(16) unsigned g_W1t[64 * 68];  // W1^T tf32, [n][k] pitch 68
__device__ __align__(16) unsigned g_W2t[64 * 68];  // W2^T tf32

// ---- TF32 MMA helpers ----
__device__ __forceinline__ unsigned cvt_tf32(float f) {
    unsigned u;
    asm("cvt.rna.tf32.f32 %0, %1;" : "=r"(u) : "f"(f));
    return u;
}
__device__ __forceinline__ void mma_tf32(float& c0, float& c1, float& c2, float& c3,
                                         unsigned a0, unsigned a1, unsigned a2, unsigned a3,
                                         unsigned b0, unsigned b1) {
    asm("mma.sync.aligned.m16n8k8.row.col.f32.tf32.tf32.f32 "
        "{%0,%1,%2,%3}, {%4,%5,%6,%7}, {%8,%9}, {%0,%1,%2,%3};"
        : "+f"(c0), "+f"(c1), "+f"(c2), "+f"(c3)
        : "r"(a0), "r"(a1), "r"(a2), "r"(a3), "r"(b0), "r"(b1));
}
__device__ __forceinline__ int batch_of(const void* batch, int r, int isI32) {
    return isI32 ? ((const int*)batch)[r] : (int)((const long long*)batch)[r];
}

// ============================================================
// K0: pack x->half, transpose+convert weights, zero pools
// ============================================================
__global__ void k_init(const float* __restrict__ x, const int* __restrict__ ei32,
                       const float* __restrict__ W1, const float* __restrict__ W2, int n8) {
    int tid = blockIdx.x * blockDim.x + threadIdx.x;
    if (tid == 0) {
        int nz = 0;
        #pragma unroll 4
        for (int i = 0; i < 256; i++) nz |= ei32[2 * i + 1];
        g_isI32 = (nz != 0) ? 1 : 0;
    }
    if (tid < n8) {
        const float4* xp = (const float4*)(x + (size_t)tid * 8);
        float4 a = xp[0], b = xp[1];
        __half2 h0 = __float22half2_rn(make_float2(a.x, a.y));
        __half2 h1 = __float22half2_rn(make_float2(a.z, a.w));
        __half2 h2 = __float22half2_rn(make_float2(b.x, b.y));
        __half2 h3 = __float22half2_rn(make_float2(b.z, b.w));
        uint4 o;
        o.x = *(unsigned*)&h0; o.y = *(unsigned*)&h1;
        o.z = *(unsigned*)&h2; o.w = *(unsigned*)&h3;
        *(uint4*)(g_xh + (size_t)tid * 8) = o;
        *(uint4*)(g_aggh + (size_t)tid * 8) = make_uint4(0u, 0u, 0u, 0u);
    }
    if (tid < 8192) {
        int w = tid >> 12;           // 0: W1, 1: W2
        int idx = tid & 4095;
        int k = idx >> 6, n = idx & 63;
        unsigned v = cvt_tf32(w ? W2[idx] : W1[idx]);
        if (w) g_W2t[n * 68 + k] = v; else g_W1t[n * 68 + k] = v;
    }
    if (tid < 128) g_stats[tid] = 0.0f;
    if (tid < NG * 64) { g_add[tid] = 0.0f; g_max[tid] = 0u; }
}

// ============================================================
// K1: edge scatter  aggh[dst] += xh[src]
// ============================================================
__global__ void k_edges(const void* __restrict__ ei, int n_edges) {
    int tid = blockIdx.x * blockDim.x + threadIdx.x;
    if (tid >= n_edges * 8) return;
    int e = tid >> 3;
    int c = tid & 7;
    int s, d;
    if (g_isI32) {
        const int* p = (const int*)ei;
        s = p[e]; d = p[n_edges + e];
    } else {
        const long long* p = (const long long*)ei;
        s = (int)p[e]; d = (int)p[n_edges + e];
    }
    uint4 v = *(const uint4*)(g_xh + ((size_t)s << 6) + (c << 3));
    __half* o = g_aggh + ((size_t)d << 6) + (c << 3);
    asm volatile("red.global.add.noftz.v4.f16x2 [%0], {%1, %2, %3, %4};"
                 :: "l"(o), "r"(v.x), "r"(v.y), "r"(v.z), "r"(v.w)
                 : "memory");
}

// ============================================================
// K2: persistent tf32-MMA GEMM1: h = (x + aggh) @ W1 + b1; BN stats
// ============================================================
__global__ __launch_bounds__(256) void k_gemm1(const float* __restrict__ x,
                                               const float* __restrict__ b1,
                                               int n_nodes, int nb) {
    __shared__ unsigned sA[64 * 68];
    __shared__ unsigned sW[64 * 68];
    __shared__ float sSum[64], sSq[64];
    int tid = threadIdx.x;

    for (int i = tid; i < 1088; i += 256)
        ((uint4*)sW)[i] = ((const uint4*)g_W1t)[i];
    if (tid < 64) { sSum[tid] = 0.0f; sSq[tid] = 0.0f; }

    int warp = tid >> 5, lane = tid & 31;
    int mtile = warp & 3, ngrp = warp >> 2;
    int gid = lane >> 2, tig = lane & 3;
    int arowL = mtile * 16 + gid;

    float bb[4][2];
    #pragma unroll
    for (int j = 0; j < 4; j++) {
        int col0 = (ngrp * 4 + j) * 8 + tig * 2;
        bb[j][0] = b1[col0]; bb[j][1] = b1[col0 + 1];
    }
    float cs[8] = {0,0,0,0,0,0,0,0}, cq[8] = {0,0,0,0,0,0,0,0};
    __syncthreads();

    for (int tile = blockIdx.x; tile < nb; tile += gridDim.x) {
        int row0 = tile * 64;
        for (int i = tid; i < 1024; i += 256) {
            int r = i >> 4, c4 = i & 15, gr = row0 + r;
            float4 v = make_float4(0.f, 0.f, 0.f, 0.f);
            if (gr < n_nodes) {
                v = *(const float4*)(x + (size_t)gr * 64 + c4 * 4);
                uint2 hh = *(const uint2*)(g_aggh + (size_t)gr * 64 + c4 * 4);
                float2 f0 = __half22float2(*(__half2*)&hh.x);
                float2 f1 = __half22float2(*(__half2*)&hh.y);
                v.x += f0.x; v.y += f0.y; v.z += f1.x; v.w += f1.y;
            }
            unsigned* p = &sA[r * 68 + c4 * 4];
            p[0] = cvt_tf32(v.x); p[1] = cvt_tf32(v.y);
            p[2] = cvt_tf32(v.z); p[3] = cvt_tf32(v.w);
        }
        __syncthreads();

        float acc[4][4];
        #pragma unroll
        for (int j = 0; j < 4; j++) {
            acc[j][0] = bb[j][0]; acc[j][1] = bb[j][1];
            acc[j][2] = bb[j][0]; acc[j][3] = bb[j][1];
        }
        #pragma unroll
        for (int kk = 0; kk < 8; kk++) {
            int k0 = kk * 8;
            unsigned a0 = sA[arowL * 68 + k0 + tig];
            unsigned a1 = sA[(arowL + 8) * 68 + k0 + tig];
            unsigned a2 = sA[arowL * 68 + k0 + tig + 4];
            unsigned a3 = sA[(arowL + 8) * 68 + k0 + tig + 4];
            #pragma unroll
            for (int j = 0; j < 4; j++) {
                int bcol = (ngrp * 4 + j) * 8 + gid;
                unsigned b0 = sW[bcol * 68 + k0 + tig];
                unsigned b1r = sW[bcol * 68 + k0 + tig + 4];
                mma_tf32(acc[j][0], acc[j][1], acc[j][2], acc[j][3], a0, a1, a2, a3, b0, b1r);
            }
        }

        int r0 = row0 + mtile * 16 + gid;
        int r1 = r0 + 8;
        #pragma unroll
        for (int j = 0; j < 4; j++) {
            int col0 = (ngrp * 4 + j) * 8 + tig * 2;
            if (r0 < n_nodes) {
                *(float2*)(g_h + (size_t)r0 * 64 + col0) = make_float2(acc[j][0], acc[j][1]);
                cs[2*j] += acc[j][0]; cs[2*j+1] += acc[j][1];
                cq[2*j] += acc[j][0] * acc[j][0]; cq[2*j+1] += acc[j][1] * acc[j][1];
            }
            if (r1 < n_nodes) {
                *(float2*)(g_h + (size_t)r1 * 64 + col0) = make_float2(acc[j][2], acc[j][3]);
                cs[2*j] += acc[j][2]; cs[2*j+1] += acc[j][3];
                cq[2*j] += acc[j][2] * acc[j][2]; cq[2*j+1] += acc[j][3] * acc[j][3];
            }
        }
        __syncthreads();
    }

    // flush stats once per block
    #pragma unroll
    for (int j = 0; j < 4; j++) {
        int col0 = (ngrp * 4 + j) * 8 + tig * 2;
        atomicAdd(&sSum[col0], cs[2*j]);   atomicAdd(&sSum[col0 + 1], cs[2*j+1]);
        atomicAdd(&sSq[col0], cq[2*j]);    atomicAdd(&sSq[col0 + 1], cq[2*j+1]);
    }
    __syncthreads();
    if (tid < 64) {
        atomicAdd(&g_stats[tid], sSum[tid]);
        atomicAdd(&g_stats[64 + tid], sSq[tid]);
    }
}

// ============================================================
// K4: persistent tf32-MMA GEMM2 + BN/ReLU + pooling
// ============================================================
__global__ __launch_bounds__(256) void k_gemm2(const float* __restrict__ b2,
                                               const float* __restrict__ gamma,
                                               const float* __restrict__ beta,
                                               const void* __restrict__ batch,
                                               int n_nodes, float inv_n, int nb) {
    __shared__ unsigned sA[64 * 68];
    __shared__ unsigned sW[64 * 68];
    __shared__ float sScale[64], sShift[64];
    int tid = threadIdx.x;

    for (int i = tid; i < 1088; i += 256)
        ((uint4*)sW)[i] = ((const uint4*)g_W2t)[i];
    if (tid < 64) {
        float mean = g_stats[tid] * inv_n;
        float var  = g_stats[64 + tid] * inv_n - mean * mean;
        float a = gamma[tid] * rsqrtf(var + 1e-5f);
        sScale[tid] = a;
        sShift[tid] = beta[tid] - mean * a;
    }

    int warp = tid >> 5, lane = tid & 31;
    int mtile = warp & 3, ngrp = warp >> 2;
    int gid = lane >> 2, tig = lane & 3;
    int arowL = mtile * 16 + gid;
    int isI32 = g_isI32;

    float bb[4][2];
    #pragma unroll
    for (int j = 0; j < 4; j++) {
        int col0 = (ngrp * 4 + j) * 8 + tig * 2;
        bb[j][0] = b2[col0]; bb[j][1] = b2[col0 + 1];
    }
    __syncthreads();

    for (int tile = blockIdx.x; tile < nb; tile += gridDim.x) {
        int row0 = tile * 64;
        for (int i = tid; i < 1024; i += 256) {
            int r = i >> 4, c4 = i & 15, gr = row0 + r, k0 = c4 * 4;
            float4 v = make_float4(0.f, 0.f, 0.f, 0.f);
            if (gr < n_nodes) {
                v = *(const float4*)(g_h + (size_t)gr * 64 + k0);
                v.x = fmaxf(v.x * sScale[k0 + 0] + sShift[k0 + 0], 0.f);
                v.y = fmaxf(v.y * sScale[k0 + 1] + sShift[k0 + 1], 0.f);
                v.z = fmaxf(v.z * sScale[k0 + 2] + sShift[k0 + 2], 0.f);
                v.w = fmaxf(v.w * sScale[k0 + 3] + sShift[k0 + 3], 0.f);
            }
            unsigned* p = &sA[r * 68 + k0];
            p[0] = cvt_tf32(v.x); p[1] = cvt_tf32(v.y);
            p[2] = cvt_tf32(v.z); p[3] = cvt_tf32(v.w);
        }
        __syncthreads();

        float acc[4][4];
        #pragma unroll
        for (int j = 0; j < 4; j++) {
            acc[j][0] = bb[j][0]; acc[j][1] = bb[j][1];
            acc[j][2] = bb[j][0]; acc[j][3] = bb[j][1];
        }
        #pragma unroll
        for (int kk = 0; kk < 8; kk++) {
            int k0 = kk * 8;
            unsigned a0 = sA[arowL * 68 + k0 + tig];
            unsigned a1 = sA[(arowL + 8) * 68 + k0 + tig];
            unsigned a2 = sA[arowL * 68 + k0 + tig + 4];
            unsigned a3 = sA[(arowL + 8) * 68 + k0 + tig + 4];
            #pragma unroll
            for (int j = 0; j < 4; j++) {
                int bcol = (ngrp * 4 + j) * 8 + gid;
                unsigned b0 = sW[bcol * 68 + k0 + tig];
                unsigned b1r = sW[bcol * 68 + k0 + tig + 4];
                mma_tf32(acc[j][0], acc[j][1], acc[j][2], acc[j][3], a0, a1, a2, a3, b0, b1r);
            }
        }

        int r0 = row0 + mtile * 16 + gid;
        int r1 = r0 + 8;
        int bi0 = (r0 < n_nodes) ? batch_of(batch, r0, isI32) : -1;
        int bi1 = (r1 < n_nodes) ? batch_of(batch, r1, isI32) : -1;
        #pragma unroll
        for (int j = 0; j < 4; j++) {
            int col0 = (ngrp * 4 + j) * 8 + tig * 2;
            float v00 = fmaxf(acc[j][0], 0.f), v01 = fmaxf(acc[j][1], 0.f);
            float v10 = fmaxf(acc[j][2], 0.f), v11 = fmaxf(acc[j][3], 0.f);
            if (bi0 >= 0 && bi0 == bi1) {
                float* pa = g_add + (size_t)bi0 * 64 + col0;
                asm volatile("red.global.add.v2.f32 [%0], {%1, %2};"
                             :: "l"(pa), "f"(v00 + v10), "f"(v01 + v11) : "memory");
                unsigned* pm = g_max + (size_t)bi0 * 64 + col0;
                atomicMax(pm,     __float_as_uint(fmaxf(v00, v10)));
                atomicMax(pm + 1, __float_as_uint(fmaxf(v01, v11)));
            } else {
                if (bi0 >= 0) {
                    float* pa = g_add + (size_t)bi0 * 64 + col0;
                    asm volatile("red.global.add.v2.f32 [%0], {%1, %2};"
                                 :: "l"(pa), "f"(v00), "f"(v01) : "memory");
                    unsigned* pm = g_max + (size_t)bi0 * 64 + col0;
                    atomicMax(pm, __float_as_uint(v00));
                    atomicMax(pm + 1, __float_as_uint(v01));
                }
                if (bi1 >= 0) {
                    float* pa = g_add + (size_t)bi1 * 64 + col0;
                    asm volatile("red.global.add.v2.f32 [%0], {%1, %2};"
                                 :: "l"(pa), "f"(v10), "f"(v11) : "memory");
                    unsigned* pm = g_max + (size_t)bi1 * 64 + col0;
                    atomicMax(pm, __float_as_uint(v10));
                    atomicMax(pm + 1, __float_as_uint(v11));
                }
            }
        }
        __syncthreads();
    }
}

// ============================================================
// K5: head MLP, 4 graphs per block
// ============================================================
__global__ __launch_bounds__(128) void k_final(const float* __restrict__ Wl1,
                                               const float* __restrict__ bl1,
                                               const float* __restrict__ Wl2,
                                               const float* __restrict__ bl2,
                                               float* __restrict__ out, int out_size) {
    int g0 = blockIdx.x * 4;
    int j = threadIdx.x;
    __shared__ float sg[4][128];
    __shared__ float red[4][128];
    #pragma unroll
    for (int q = 0; q < 4; q++) {
        int g = g0 + q;
        sg[q][j] = (j < 64) ? g_add[g * 64 + j]
                            : __uint_as_float(g_max[g * 64 + (j - 64)]);
    }
    __syncthreads();
    float bj = bl1[j];
    float t[4] = {bj, bj, bj, bj};
    #pragma unroll 4
    for (int k = 0; k < 128; k++) {
        float w = Wl1[k * 128 + j];
        #pragma unroll
        for (int q = 0; q < 4; q++) t[q] += sg[q][k] * w;
    }
    float w2 = Wl2[j];
    #pragma unroll
    for (int q = 0; q < 4; q++) red[q][j] = fmaxf(t[q], 0.f) * w2;
    __syncthreads();
    for (int sft = 64; sft > 0; sft >>= 1) {
        if (j < sft) {
            #pragma unroll
            for (int q = 0; q < 4; q++) red[q][j] += red[q][j + sft];
        }
        __syncthreads();
    }
    if (j < 4) {
        float logit = red[j][0] + bl2[0];
        int g = g0 + j;
        out[g] = 1.0f / (1.0f + expf(-logit));
        if (out_size >= 2 * NG) out[NG + g] = logit;
    }
}

// ============================================================
extern "C" void kernel_launch(void* const* d_in, const int* in_sizes, int n_in,
                              void* d_out, int out_size) {
    const float* x     = (const float*)d_in[0];
    const void*  ei    = d_in[1];
    const void*  batch = d_in[2];
    const float* W1    = (const float*)d_in[3];
    const float* b1    = (const float*)d_in[4];
    const float* gamma = (const float*)d_in[5];
    const float* beta  = (const float*)d_in[6];
    const float* W2    = (const float*)d_in[7];
    const float* b2    = (const float*)d_in[8];
    const float* Wl1   = (const float*)d_in[9];
    const float* bl1   = (const float*)d_in[10];
    const float* Wl2   = (const float*)d_in[11];
    const float* bl2   = (const float*)d_in[12];
    float* out = (float*)d_out;

    int n_nodes = in_sizes[0] / 64;
    if (n_nodes > NMAX) n_nodes = NMAX;
    int n_edges = in_sizes[1] / 2;

    int n8 = n_nodes * 8;
    int initN = (n8 > NG * 64) ? n8 : NG * 64;
    k_init<<<(initN + 255) / 256, 256>>>(x, (const int*)ei, W1, W2, n8);

    long long etot = (long long)n_edges * 8;
    k_edges<<<(int)((etot + 255) / 256), 256>>>(ei, n_edges);

    int nb = (n_nodes + 63) / 64;
    int grid = nb < 296 ? nb : 296;
    k_gemm1<<<grid, 256>>>(x, b1, n_nodes, nb);
    k_gemm2<<<grid, 256>>>(b2, gamma, beta, batch, n_nodes, 1.0f / (float)n_nodes, nb);
    k_final<<<NG / 4, 128>>>(Wl1, bl1, Wl2, bl2, out, out_size);
}